// round 17
// baseline (speedup 1.0000x reference)
#include <cuda_runtime.h>
#include <cstdint>

// Shapes (fixed): B=128, CIN=16, COUT=16, F=512, N=32, K=2
#define BB   128
#define CI   16
#define CO   16
#define FF   512
#define NN   32
#define NTILES ((BB * FF) / 16)   // 4096 tiles of 16 (b,f)-rows
#define GRID   304                // 2 persistent blocks / SM

// g_W layout [i][c][n] packed u64 (k0,k1);  g_Bias [c][n]
__device__ uint64_t g_W[CI * CO * NN];
__device__ float    g_Bias[CO * NN];

#define SW_CNT    (CI * CO * NN)
#define SB_BYTES  (CO * NN * 4)
#define SX_OFF    (SW_CNT * 8 + SB_BYTES)      // 67584
#define STAGE_BYTES 8192                        // 8 warps x 1KB per stage
#define NSTAGE    3
#define SMEM_BYTES (SX_OFF + NSTAGE * STAGE_BYTES)   // 92160

__device__ __forceinline__ uint64_t pack2(float lo, float hi) {
    uint64_t r;
    asm("mov.b64 %0, {%1, %2};" : "=l"(r) : "f"(lo), "f"(hi));
    return r;
}
__device__ __forceinline__ void ffma2(uint64_t& acc, uint64_t a, uint64_t b) {
    asm("fma.rn.f32x2 %0, %1, %2, %0;" : "+l"(acc) : "l"(a), "l"(b));
}
__device__ __forceinline__ void stcs64(uint64_t* p, uint64_t v) {
    asm volatile("st.global.cs.b64 [%0], %1;" :: "l"(p), "l"(v) : "memory");
}
__device__ __forceinline__ uint32_t smem_u32(const void* p) {
    uint32_t a;
    asm("{ .reg .u64 t; cvta.to.shared.u64 t, %1; cvt.u32.u64 %0, t; }" : "=r"(a) : "l"(p));
    return a;
}
__device__ __forceinline__ void cpasync16(uint32_t dst, const float* src) {
    asm volatile("cp.async.ca.shared.global [%0], [%1], 16;" :: "r"(dst), "l"(src));
}
__device__ __forceinline__ void cp_commit() {
    asm volatile("cp.async.commit_group;");
}
template <int N>
__device__ __forceinline__ void cp_wait() {
    asm volatile("cp.async.wait_group %0;" :: "n"(N));
}

// ---------------------------------------------------------------------------
// Prologue kernel (separate launch — every fusion attempt spilled).
// ---------------------------------------------------------------------------
__global__ void prep_kernel(const float* __restrict__ W1, const float* __restrict__ b1,
                            const float* __restrict__ W2, const float* __restrict__ b2)
{
    const int t = blockIdx.x * blockDim.x + threadIdx.x;
    if (t < CI * CO * NN) {
        const int n = t & 31;
        const int c = (t >> 5) & 15;
        const int i = t >> 9;
        float s0 = 0.f, s1 = 0.f;
        const float2* w1 = (const float2*)(W1 + ((size_t)(n * CI + i) * CO) * 2);
        const float*  w2 = W2 + (size_t)n * CO * CO + c;
#pragma unroll
        for (int o = 0; o < CO; ++o) {
            float2 a = __ldg(w1 + o);
            float  wv = __ldg(w2 + o * CO);
            s0 = fmaf(a.x, wv, s0);
            s1 = fmaf(a.y, wv, s1);
        }
        g_W[(i * CO + c) * NN + n] = pack2(s0, s1);
    }
    if (t < CO * NN) {
        const int n = t & 31;
        const int c = t >> 5;
        float s = __ldg(b2 + n * CO + c);
#pragma unroll
        for (int o = 0; o < CO; ++o)
            s = fmaf(__ldg(b1 + n * CO + o), __ldg(W2 + (size_t)(n * CO + o) * CO + c), s);
        g_Bias[c * NN + n] = s;
    }
}

// ---------------------------------------------------------------------------
// Main kernel: x staged per-warp in smem via cp.async
// (3-stage, distance-2, warp-private -> no block barriers, no x registers).
// Stage layout: byte offset = SX_OFF + s*STAGE_BYTES + warp*1024 + row*128 + n*4
// ---------------------------------------------------------------------------
__global__ __launch_bounds__(256, 2)
void up_kernel(const float* __restrict__ x, float* __restrict__ out)
{
    extern __shared__ uint64_t sW[];              // [i][c][n] u64 : 64 KB
    float* sBias = (float*)(sW + SW_CNT);         // [c][n]        :  2 KB
    char*  smemc = (char*)sW;

    const int tid = threadIdx.x;
    {
        const uint4* gw = (const uint4*)g_W;
        uint4* sw4 = (uint4*)sW;
#pragma unroll
        for (int idx = tid; idx < SW_CNT / 2; idx += 256)
            sw4[idx] = gw[idx];
        for (int idx = tid; idx < CO * NN; idx += 256)
            sBias[idx] = g_Bias[idx];
    }
    __syncthreads();

    const int lane = tid & 31;           // n (consumer role)
    const int warp = tid >> 5;
    const int c0   = (warp & 3) * 4;     // 4 channels per warp
    const int g    = warp >> 2;          // row half (rows g*8 .. g*8+7)

    // fill-role lane mapping: rows rr & rr+4, 16B column cc16
    const int rr   = lane >> 3;          // 0..3
    const int cc16 = lane & 7;           // 0..7

    uint64_t bp[4];
#pragma unroll
    for (int cc = 0; cc < 4; ++cc) {
        float bv = sBias[(c0 + cc) * NN + lane];
        bp[cc] = pack2(bv, bv);
    }

    const uint64_t* wbase = sW + c0 * NN + lane;

    // this warp's x staging area (1 KB slot inside each 8 KB stage)
    const uint32_t sxw = smem_u32(smemc + SX_OFF) + warp * 1024;
    const float*   sxf = (const float*)(smemc + SX_OFF + warp * 1024);

    for (int tile = blockIdx.x; tile < NTILES; tile += GRID) {
        const int rowbase = tile * 16 + g * 8;
        const int b = rowbase >> 9;
        const int f = rowbase & (FF - 1);

        // gmem base of this warp's 8 rows for input channel 0
        const float* xt = x + ((size_t)b * CI * FF + f) * NN;

        uint64_t acc[8][4];
#pragma unroll
        for (int cc = 0; cc < 4; ++cc)
#pragma unroll
            for (int r = 0; r < 8; ++r) acc[r][cc] = bp[cc];

        // prologue: fill stages 0,1 with i=0,1
#pragma unroll
        for (int pi = 0; pi < 2; ++pi) {
            const float* gsrc = xt + (size_t)pi * (FF * NN);
            cpasync16(sxw + pi * STAGE_BYTES + rr * 128 + cc16 * 16,
                      gsrc + rr * NN + cc16 * 4);
            cpasync16(sxw + pi * STAGE_BYTES + (rr + 4) * 128 + cc16 * 16,
                      gsrc + (rr + 4) * NN + cc16 * 4);
            cp_commit();
        }

#pragma unroll
        for (int i = 0; i < CI; ++i) {
            const int s = i % NSTAGE;

            // issue fill for i+2 into stage (i+2)%3
            if (i + 2 < CI) {
                const int s2 = (i + 2) % NSTAGE;
                const float* gsrc = xt + (size_t)(i + 2) * (FF * NN);
                cpasync16(sxw + s2 * STAGE_BYTES + rr * 128 + cc16 * 16,
                          gsrc + rr * NN + cc16 * 4);
                cpasync16(sxw + s2 * STAGE_BYTES + (rr + 4) * 128 + cc16 * 16,
                          gsrc + (rr + 4) * NN + cc16 * 4);
                cp_commit();
            }

            // wait until fill(i) complete (compile-time pending count)
            if (i + 2 < CI)      cp_wait<2>();
            else if (i + 1 < CI) cp_wait<1>();
            else                 cp_wait<0>();
            __syncwarp();

            uint64_t w[4];
#pragma unroll
            for (int cc = 0; cc < 4; ++cc)
                w[cc] = wbase[(i * CO + cc) * NN];

#pragma unroll
            for (int r = 0; r < 8; ++r) {
                // FIXED (R16 bug): stage stride is 8192 B = 2048 floats.
                // byte addr = s*8192 + r*128 + lane*4  (conflict-free)
                const float xs = sxf[s * 2048 + r * 32 + lane];
                const uint64_t xv = pack2(xs, xs);
#pragma unroll
                for (int cc = 0; cc < 4; ++cc)
                    ffma2(acc[r][cc], xv, w[cc]);
            }
        }

        // out[b, c0+cc, f+r, 2n+k] as u64 — coalesced 256B streaming stores
        uint64_t* op = (uint64_t*)out + (((size_t)b * CO + c0) * FF + f) * NN + lane;
#pragma unroll
        for (int cc = 0; cc < 4; ++cc)
#pragma unroll
            for (int r = 0; r < 8; ++r)
                stcs64(op + ((size_t)cc * FF + r) * NN, acc[r][cc]);
    }
}

// ---------------------------------------------------------------------------
extern "C" void kernel_launch(void* const* d_in, const int* in_sizes, int n_in,
                              void* d_out, int out_size)
{
    const float* x  = (const float*)d_in[0];
    const float* W1 = (const float*)d_in[1];
    const float* b1 = (const float*)d_in[2];
    const float* W2 = (const float*)d_in[3];
    const float* b2 = (const float*)d_in[4];
    float* out = (float*)d_out;

    prep_kernel<<<64, 128>>>(W1, b1, W2, b2);

    cudaFuncSetAttribute(up_kernel, cudaFuncAttributeMaxDynamicSharedMemorySize,
                         SMEM_BYTES);
    up_kernel<<<GRID, 256, SMEM_BYTES>>>(x, out);
}